// round 16
// baseline (speedup 1.0000x reference)
#include <cuda_runtime.h>
#include <cuda_fp16.h>
#include <math.h>
#include <stdint.h>

// ---------------- problem constants ----------------
#define LLn   144
#define DIN   1024
#define DT    150
#define DTP   160
#define NOUT  4
#define BL    288
#define BZO   1152
#define OI    600
#define NFLAT 90000          // OI*DT      (flattened op1 N)
#define NF2   86400          // 576*DT     (flattened op2 N per batch)
#define NF3   82944          // 576*LLn    (flattened op3 N per batch)
#define OUT1N 23887872
#define LOGQ  -1.3862943611198906f
#define PITCH 144            // smem row pitch bytes (64 k fp16 = 128B + 16 pad)

// ---------------- scratch (device globals, fp16) -------------
// x keeps hi/lo split (proj GEMM exact to ~2^-22); everything downstream single.
// pad cols [150,160) never written -> stay zero, as K=160 consumers need.
__device__ __align__(256) __half g_xh[BL*DIN],  g_xl[BL*DIN];
__device__ __align__(256) __half g_Wp[4][DT*DIN];                  // [sel][n][k]
__device__ __align__(256) __half g_Wt[2][OI*DT*DTP];               // [tri][(oi,j)][k]
__device__ __align__(256) __half g_p[4][BL*DTP];                   // projections (single)
__device__ __align__(256) __half g_w[2][(size_t)BZO*DT*DTP];
// g_t rows per batch: (z*144+y)*4+o  (o innermost -> softmax quads adjacent)
__device__ __align__(256) __half g_t[2][(size_t)BZO*LLn*DTP];

// ---------------- helpers ----------------
__device__ __forceinline__ void split2(float v, __half& h, __half& l) {
    h = __float2half_rn(v);
    l = __float2half_rn(v - __half2float(h));
}
__device__ __forceinline__ void store_pair1(__half* base, size_t d, float v0, float v1) {
    uint32_t p = (uint32_t)__half_as_ushort(__float2half_rn(v0))
               | ((uint32_t)__half_as_ushort(__float2half_rn(v1)) << 16);
    *(uint32_t*)(base + d) = p;
}
__device__ __forceinline__ uint32_t smem_u32(const void* p) {
    uint32_t a;
    asm("{ .reg .u64 t; cvta.to.shared.u64 t, %1; cvt.u32.u64 %0, t; }" : "=r"(a) : "l"(p));
    return a;
}
__device__ __forceinline__ void ldm4(uint32_t* d, uint32_t addr) {
    asm volatile("ldmatrix.sync.aligned.m8n8.x4.shared.b16 {%0,%1,%2,%3}, [%4];"
        : "=r"(d[0]), "=r"(d[1]), "=r"(d[2]), "=r"(d[3]) : "r"(addr));
}
__device__ __forceinline__ void mma_f16(float* c, const uint32_t* a, uint32_t b0, uint32_t b1) {
    asm volatile("mma.sync.aligned.m16n8k16.row.col.f32.f16.f16.f32 "
        "{%0,%1,%2,%3}, {%4,%5,%6,%7}, {%8,%9}, {%0,%1,%2,%3};"
        : "+f"(c[0]), "+f"(c[1]), "+f"(c[2]), "+f"(c[3])
        : "r"(a[0]), "r"(a[1]), "r"(a[2]), "r"(a[3]), "r"(b0), "r"(b1));
}
__device__ __forceinline__ void cpa16(uint32_t dst, const void* src, uint32_t sz) {
    asm volatile("cp.async.cg.shared.global [%0], [%1], 16, %2;"
        :: "r"(dst), "l"(src), "r"(sz) : "memory");
}
template<int N> __device__ __forceinline__ void cp_wait() {
    asm volatile("cp.async.wait_group %0;" :: "n"(N) : "memory");
}
__device__ __forceinline__ float4 lsm4(float a, float b, float c, float d) {
    float m = fmaxf(fmaxf(a, b), fmaxf(c, d));
    float s = expf(a - m) + expf(b - m) + expf(c - m) + expf(d - m);
    float l = m + logf(s);
    return make_float4(a - l, b - l, c - l, d - l);
}

// ---------------- prep kernels ----------------
__global__ void prep_x(const float* __restrict__ x) {
    int i = blockIdx.x * 256 + threadIdx.x;
    if (i >= BL * DIN) return;
    split2(x[i], g_xh[i], g_xl[i]);
}
__global__ void prep_pw4(const float* __restrict__ W0, const float* __restrict__ W1,
                         const float* __restrict__ W2, const float* __restrict__ W3) {
    int i = blockIdx.x * 256 + threadIdx.x;
    if (i >= DT * DIN) return;
    int sel = blockIdx.y;
    const float* W = (sel == 0) ? W0 : (sel == 1) ? W1 : (sel == 2) ? W2 : W3;
    int n = i >> 10, k = i & 1023;
    g_Wp[sel][i] = __float2half_rn(__ldg(&W[k * DT + n]));
}
__global__ void prep_wt2(const float* __restrict__ Wa, const float* __restrict__ Wb) {
    __shared__ float t[32][33];
    int oi = blockIdx.x;
    int tri = blockIdx.z;
    const float* W = tri ? Wb : Wa;
    int kt = (blockIdx.y / 5) * 32, jt = (blockIdx.y % 5) * 32;
    int tx = threadIdx.x, ty = threadIdx.y;
    int k = kt + ty, j = jt + tx;
    float v = (k < DT && j < DT) ? W[(size_t)oi * (DT * DT) + k * DT + j] : 0.f;
    t[ty][tx] = v;
    __syncthreads();
    int j2 = jt + ty, k2 = kt + tx;
    if (j2 < DT && k2 < DTP) {
        float u = t[tx][ty];
        size_t d = (size_t)oi * (DT * DTP) + (size_t)j2 * DTP + k2;
        g_Wt[tri][d] = __float2half_rn(u);
    }
}

// ---------------- HMMA GEMM: BM=48, BN=96, BK=64 superchunk, 192 thr -------
// smem rows pitch 144B. MODE0: A hi/lo split; modes 1-3 single x single.
// Warp grid 3(m) x 2(n): each warp 16m x 48n = 6 acc quads; 24 MMA/superchunk.
// MODE 0: proj   x(288x1024) @ Wp[z] -> g_p[z]              (z=sel, 4 stages)
// MODE 1: op1    p0(288xDTP) @ Wt[z] flat N=90000 -> g_w[z]  (z=tri)
// MODE 2: op2    Y @ g_w[tr][b] flat N=86400 -> g_t[tr]      (z=b*2+tr)
// MODE 3: op3    X @ g_t[tr][b] flat N=82944 -> out (+tr ofs) (z=b*2+tr),
//                fused mask+logsoftmax; tr=0 direct, tr=1 transposed coords
template<int MODE, int STAGES>
__global__ __launch_bounds__(192)
void tk(const float* __restrict__ b0s, const float* __restrict__ b1s,
        const float* __restrict__ b2s, const float* __restrict__ b3s,
        float* __restrict__ outp)
{
    constexpr bool ASPLIT = (MODE == 0);
    constexpr int OFFAL = 48 * PITCH;                    // 6912 (Al region, split only)
    constexpr int OFFB  = ASPLIT ? 2 * OFFAL : OFFAL;    // 13824 / 6912
    constexpr int STGc  = OFFB + 96 * PITCH;             // 27648 / 20736
    constexpr int NITc  = ASPLIT ? 8 : 6;                // 1536 / 1152 segments
    constexpr int Klim  = (MODE == 0) ? DIN : DTP;

    extern __shared__ __align__(16) char sm[];

    const int tid  = threadIdx.x;
    const int lane = tid & 31, warp = tid >> 5;
    const int wm = warp >> 1, wn = warp & 1;
    const int bx = blockIdx.x, by = blockIdx.y, zb = blockIdx.z;
    const int m0 = bx * 48, n0 = by * 96;

    // OP3 decode
    const int tr = zb & 1, bb = zb >> 1;
    float* outO = nullptr;
    if constexpr (MODE == 3) outO = outp + (size_t)tr * OUT1N;

    // ---- OP3 fully-masked block: fill constants, skip GEMM ----
    if constexpr (MODE == 3) {
        bool allmask;
        if (!tr) {
            allmask = ((n0 >> 2) / LLn) > (m0 + 47);
        } else {
            allmask = true;
            #pragma unroll 1
            for (int qd = 0; qd < 24; qd++) {
                int nq = (n0 >> 2) + qd;
                if (nq / LLn <= nq % LLn) { allmask = false; break; }
            }
        }
        if (allmask) {
            const float4 c4 = make_float4(LOGQ, LOGQ, LOGQ, LOGQ);
            for (int idx = tid; idx < 48 * 24; idx += 192) {
                int mm = m0 + idx / 24;
                int nq = (n0 >> 2) + idx % 24;
                int z = nq / LLn, t = nq % LLn;
                size_t qb;
                if (!tr) qb = (((size_t)(bb * LLn + z) * LLn + mm) * LLn + t);
                else     qb = (((size_t)(bb * LLn + z) * LLn + t) * LLn + mm);
                ((float4*)outO)[qb] = c4;
            }
            return;
        }
    }

    const __half *Ah, *Al = nullptr, *Bh;
    int pitchA, pitchB, KT, NB;
    if constexpr (MODE == 0) {
        Ah = g_xh; Al = g_xl; Bh = g_Wp[zb];
        pitchA = DIN; pitchB = DIN; KT = 16; NB = DT;
    }
    if constexpr (MODE == 1) {
        Ah = g_p[0]; Bh = g_Wt[zb];
        pitchA = DTP; pitchB = DTP; KT = 3; NB = NFLAT;
    }
    if constexpr (MODE == 2) {
        const int sl = tr ? 1 : 2;                 // tri1: Y=oh, tri2: Y=st
        Ah = g_p[sl] + (size_t)bb * LLn * DTP;
        Bh = g_w[tr] + (size_t)bb * 576 * DT * DTP;
        pitchA = DTP; pitchB = DTP; KT = 3; NB = NF2;
    }
    if constexpr (MODE == 3) {
        Ah = g_p[tr ? 3 : 1] + (size_t)bb * LLn * DTP;
        Bh = g_t[tr] + (size_t)bb * NF3 * DTP;
        pitchA = DTP; pitchB = DTP; KT = 3; NB = NF3;
    }

    const uint32_t sbase = smem_u32(sm);

    // ---- per-thread staging plan: NITc 16B segments per superchunk ----
    const __half* sptr[NITc];
    uint32_t sdst[NITc], ssz[NITc], skoff[NITc];
    constexpr int NA = ASPLIT ? 768 : 384;
    #pragma unroll
    for (int it = 0; it < NITc; it++) {
        int idx = tid + it * 192;
        if (idx < NA) {
            int mat = idx / 384;                     // 0=Ah 1=Al (split only)
            int rem = idx - mat * 384;
            int row = rem >> 3, seg = rem & 7;
            sptr[it] = ((mat && ASPLIT) ? Al : Ah) + (size_t)(m0 + row) * pitchA + seg * 8;
            sdst[it] = (uint32_t)(mat * OFFAL + row * PITCH + seg * 16);
            ssz[it]  = 16;
            skoff[it] = (uint32_t)(seg * 8);
        } else {
            int brem = idx - NA;                     // B rows 96 x 8 segs
            int row = brem >> 3, seg = brem & 7;
            int gr = n0 + row;
            bool vv = gr < NB;
            sptr[it] = Bh + (size_t)(vv ? gr : n0) * pitchB + seg * 8;
            sdst[it] = (uint32_t)(OFFB + row * PITCH + seg * 16);
            ssz[it]  = vv ? 16u : 0u;
            skoff[it] = (uint32_t)(seg * 8);
        }
    }

    // ---- ldmatrix lane offsets (pitch-144 rows, conflict-free) ----
    const int q = lane >> 3, r = lane & 7;
    const uint32_t aOff  = (uint32_t)((wm * 16 + ((q & 1) ? 8 : 0) + r) * PITCH + ((q >> 1) ? 16 : 0));
    const uint32_t bOff0 = (uint32_t)((wn * 48 + ((lane >> 4) ? 8 : 0) + r) * PITCH + ((q & 1) ? 16 : 0));

    // OP3/tri0: warp-level compute skip when warp's m-range fully masked
    bool wskip = false;
    if constexpr (MODE == 3)
        wskip = (!tr) && (((n0 >> 2) / LLn) > (m0 + wm * 16 + 15));

    float acc[6][4];
    #pragma unroll
    for (int i = 0; i < 6; i++)
        #pragma unroll
        for (int j = 0; j < 4; j++) acc[i][j] = 0.f;

    auto stageCh = [&](int buf, int kbase) {
        const uint32_t sb = sbase + (uint32_t)(buf * STGc);
        const uint32_t rem = (uint32_t)(Klim - kbase);
        #pragma unroll
        for (int it = 0; it < NITc; it++) {
            uint32_t sz = (skoff[it] + 8 <= rem) ? ssz[it] : 0u;
            cpa16(sb + sdst[it], sptr[it], sz);
            sptr[it] += 64;
        }
        asm volatile("cp.async.commit_group;" ::: "memory");
    };

    // prologue: stage first STAGES-1 superchunks
    #pragma unroll
    for (int s = 0; s < STAGES - 1 && s < KT; s++) stageCh(s, s * 64);

    for (int ch = 0; ch < KT; ch++) {
        if (ch + STAGES - 1 < KT) {
            stageCh((ch + STAGES - 1) & (STAGES - 1), (ch + STAGES - 1) * 64);
            cp_wait<STAGES - 1>();
        } else {
            if constexpr (STAGES == 2) {
                cp_wait<0>();
            } else {
                int v = KT - 1 - ch;
                if (v >= 2) cp_wait<2>();
                else if (v == 1) cp_wait<1>();
                else cp_wait<0>();
            }
        }
        __syncthreads();

        if (!wskip) {
            const uint32_t cb = sbase + (uint32_t)((ch & (STAGES - 1)) * STGc);
            const int kslim = min(4, (Klim - ch * 64) >> 4);
            #pragma unroll
            for (int ks = 0; ks < 4; ks++) {
                if (ks >= kslim) break;
                const uint32_t ko = (uint32_t)(ks * 32);
                uint32_t ah[4], al4[4];
                ldm4(ah, cb + aOff + ko);
                if constexpr (ASPLIT) ldm4(al4, cb + OFFAL + aOff + ko);
                #pragma unroll
                for (int g = 0; g < 3; g++) {
                    uint32_t bh[4];
                    const uint32_t bo = bOff0 + (uint32_t)(g * 16 * PITCH) + ko;
                    ldm4(bh, cb + OFFB + bo);
                    mma_f16(acc[2 * g],     ah,  bh[0], bh[1]);
                    mma_f16(acc[2 * g + 1], ah,  bh[2], bh[3]);
                    if constexpr (ASPLIT) {
                        mma_f16(acc[2 * g],     al4, bh[0], bh[1]);
                        mma_f16(acc[2 * g + 1], al4, bh[2], bh[3]);
                    }
                }
            }
        }
        __syncthreads();
    }

    // ---- store ----
    const float* bias = nullptr;
    if constexpr (MODE == 0)
        bias = (zb == 0) ? b0s : (zb == 1) ? b1s : (zb == 2) ? b2s : b3s;

    const int g8 = lane >> 2, cc = lane & 3, t2 = cc * 2;
    const int mb = m0 + wm * 16, nbb = n0 + wn * 48;

    if constexpr (MODE <= 2) {
        // pair-packed stores (even n; rows even-width so pairs never straddle)
        #pragma unroll
        for (int j = 0; j < 6; j++) {
            #pragma unroll
            for (int h = 0; h < 2; h++) {
                const int m = mb + g8 + h * 8;
                const int n = nbb + j * 8 + t2;          // even
                const float v0 = acc[j][2 * h], v1 = acc[j][2 * h + 1];
                if constexpr (MODE == 0) {
                    if (n + 1 < DTP) {
                        float a0 = (n < DT) ? v0 + bias[n] : 0.f;
                        float a1 = (n + 1 < DT) ? v1 + bias[n + 1] : 0.f;
                        store_pair1(g_p[zb], (size_t)m * DTP + n, a0, a1);
                    }
                }
                if constexpr (MODE == 1) {
                    if (n < NFLAT) {
                        int oi = n / DT, jj = n - oi * DT;
                        int o = oi / DT, i = oi - o * DT;
                        size_t d = ((size_t)(m * NOUT + o) * DT + i) * DTP + jj;
                        store_pair1(g_w[zb], d, v0, v1);
                    }
                }
                if constexpr (MODE == 2) {
                    int qq = n / DT, i = n - qq * DT;
                    int z = qq >> 2, o = qq & 3;
                    size_t rrow = ((size_t)(z * LLn + m)) * NOUT + o;
                    size_t d = ((size_t)bb * NF3 + rrow) * DTP + i;
                    store_pair1(g_t[tr], d, v0, v1);
                }
            }
        }
    } else {
        // fused mask + log_softmax; one float4 per quad, even-cc lanes store
        #pragma unroll
        for (int j = 0; j < 6; j++) {
            #pragma unroll
            for (int h = 0; h < 2; h++) {
                const float a0 = acc[j][2 * h], a1 = acc[j][2 * h + 1];
                const float p0 = __shfl_xor_sync(0xffffffffu, a0, 1);
                const float p1 = __shfl_xor_sync(0xffffffffu, a1, 1);
                if (!(cc & 1)) {
                    const int nq = (nbb + j * 8 + ((cc == 2) ? 4 : 0)) >> 2;
                    const int z = nq / LLn, t = nq - z * LLn;
                    const int m = mb + g8 + h * 8;
                    const bool keep = tr ? (z <= t) : (z <= m);
                    float4 r4;
                    if (keep) r4 = lsm4(a0, a1, p0, p1);
                    else      r4 = make_float4(LOGQ, LOGQ, LOGQ, LOGQ);
                    size_t qb;
                    if (!tr) qb = (((size_t)(bb * LLn + z) * LLn + m) * LLn + t);
                    else     qb = (((size_t)(bb * LLn + z) * LLn + t) * LLn + m);
                    ((float4*)outO)[qb] = r4;
                }
            }
        }
    }
}

// ---------------------------------------------------------------------------
extern "C" void kernel_launch(void* const* d_in, const int* in_sizes, int n_in,
                              void* d_out, int out_size)
{
    const float* x     = (const float*)d_in[0];
    const float* W_sh  = (const float*)d_in[1];
    const float* b_sh  = (const float*)d_in[2];
    const float* W_st  = (const float*)d_in[3];
    const float* b_st  = (const float*)d_in[4];
    const float* W_oh  = (const float*)d_in[5];
    const float* b_oh  = (const float*)d_in[6];
    const float* W_ot  = (const float*)d_in[7];
    const float* b_ot  = (const float*)d_in[8];
    const float* W_t1  = (const float*)d_in[9];
    const float* W_t2  = (const float*)d_in[10];
    float* out = (float*)d_out;

    cudaFuncSetAttribute(tk<0, 4>, cudaFuncAttributeMaxDynamicSharedMemorySize, 4 * 27648);
    cudaFuncSetAttribute(tk<1, 2>, cudaFuncAttributeMaxDynamicSharedMemorySize, 2 * 20736);
    cudaFuncSetAttribute(tk<2, 2>, cudaFuncAttributeMaxDynamicSharedMemorySize, 2 * 20736);
    cudaFuncSetAttribute(tk<3, 2>, cudaFuncAttributeMaxDynamicSharedMemorySize, 2 * 20736);

    // prep: fp16 conversions (x h/l split; weights single)
    prep_x<<<(BL * DIN + 255) / 256, 256>>>(x);
    prep_pw4<<<dim3((DT * DIN + 255) / 256, 4), 256>>>(W_sh, W_st, W_oh, W_ot);
    prep_wt2<<<dim3(OI, 25, 2), dim3(32, 32)>>>(W_t1, W_t2);

    // projections: M=288 (6x48) x N=150 (2x96) x 4 sel, 4-stage pipeline
    tk<0, 4><<<dim3(6, 2, 4), 192, 4 * 27648>>>(b_sh, b_st, b_oh, b_ot, nullptr);

    // op1 both tris:  z = tri
    tk<1, 2><<<dim3(6, 938, 2), 192, 2 * 20736>>>(nullptr, nullptr, nullptr, nullptr, nullptr);
    // op2 both tris x both batches: z = b*2 + tri
    tk<2, 2><<<dim3(3, 900, 4), 192, 2 * 20736>>>(nullptr, nullptr, nullptr, nullptr, nullptr);
    // op3 both tris x both batches (merged): z = b*2 + tri
    tk<3, 2><<<dim3(3, 864, 4), 192, 2 * 20736>>>(nullptr, nullptr, nullptr, nullptr, out);
}

// round 17
// speedup vs baseline: 1.0013x; 1.0013x over previous
#include <cuda_runtime.h>
#include <cuda_fp16.h>
#include <math.h>
#include <stdint.h>

// ---------------- problem constants ----------------
#define LLn   144
#define DIN   1024
#define DT    150
#define DTP   160
#define NOUT  4
#define BL    288
#define BZO   1152
#define OI    600
#define NFLAT 90000          // OI*DT      (flattened op1 N)
#define NF2   86400          // 576*DT     (flattened op2 N per batch)
#define NF3   82944          // 576*LLn    (flattened op3 N per batch)
#define OUT1N 23887872
#define LOGQ  -1.3862943611198906f

// ---------------- scratch (device globals, fp16) -------------
// x keeps hi/lo split (proj GEMM exact to ~2^-22); everything downstream single.
// pad cols [150,160) never written -> stay zero, as K=160 consumers need.
__device__ __align__(256) __half g_xh[BL*DIN],  g_xl[BL*DIN];
__device__ __align__(256) __half g_Wp[4][DT*DIN];                  // [sel][n][k]
__device__ __align__(256) __half g_Wt[2][OI*DT*DTP];               // [tri][(oi,j)][k]
__device__ __align__(256) __half g_p[4][BL*DTP];                   // projections (single)
__device__ __align__(256) __half g_w[2][(size_t)BZO*DT*DTP];
// g_t rows per batch: (z*144+y)*4+o  (o innermost -> softmax quads adjacent)
__device__ __align__(256) __half g_t[2][(size_t)BZO*LLn*DTP];

// ---------------- helpers ----------------
__device__ __forceinline__ void split2(float v, __half& h, __half& l) {
    h = __float2half_rn(v);
    l = __float2half_rn(v - __half2float(h));
}
__device__ __forceinline__ void store_pair1(__half* base, size_t d, float v0, float v1) {
    uint32_t p = (uint32_t)__half_as_ushort(__float2half_rn(v0))
               | ((uint32_t)__half_as_ushort(__float2half_rn(v1)) << 16);
    *(uint32_t*)(base + d) = p;
}
__device__ __forceinline__ uint32_t smem_u32(const void* p) {
    uint32_t a;
    asm("{ .reg .u64 t; cvta.to.shared.u64 t, %1; cvt.u32.u64 %0, t; }" : "=r"(a) : "l"(p));
    return a;
}
__device__ __forceinline__ void ldm4(uint32_t* d, uint32_t addr) {
    asm volatile("ldmatrix.sync.aligned.m8n8.x4.shared.b16 {%0,%1,%2,%3}, [%4];"
        : "=r"(d[0]), "=r"(d[1]), "=r"(d[2]), "=r"(d[3]) : "r"(addr));
}
__device__ __forceinline__ void mma_f16(float* c, const uint32_t* a, uint32_t b0, uint32_t b1) {
    asm volatile("mma.sync.aligned.m16n8k16.row.col.f32.f16.f16.f32 "
        "{%0,%1,%2,%3}, {%4,%5,%6,%7}, {%8,%9}, {%0,%1,%2,%3};"
        : "+f"(c[0]), "+f"(c[1]), "+f"(c[2]), "+f"(c[3])
        : "r"(a[0]), "r"(a[1]), "r"(a[2]), "r"(a[3]), "r"(b0), "r"(b1));
}
__device__ __forceinline__ void cpa16(uint32_t dst, const void* src, uint32_t sz) {
    asm volatile("cp.async.cg.shared.global [%0], [%1], 16, %2;"
        :: "r"(dst), "l"(src), "r"(sz) : "memory");
}
template<int N> __device__ __forceinline__ void cp_wait() {
    asm volatile("cp.async.wait_group %0;" :: "n"(N) : "memory");
}
__device__ __forceinline__ float4 lsm4(float a, float b, float c, float d) {
    float m = fmaxf(fmaxf(a, b), fmaxf(c, d));
    float s = expf(a - m) + expf(b - m) + expf(c - m) + expf(d - m);
    float l = m + logf(s);
    return make_float4(a - l, b - l, c - l, d - l);
}

// ---------------- prep kernels ----------------
__global__ void prep_x(const float* __restrict__ x) {
    int i = blockIdx.x * 256 + threadIdx.x;
    if (i >= BL * DIN) return;
    split2(x[i], g_xh[i], g_xl[i]);
}
__global__ void prep_pw4(const float* __restrict__ W0, const float* __restrict__ W1,
                         const float* __restrict__ W2, const float* __restrict__ W3) {
    int i = blockIdx.x * 256 + threadIdx.x;
    if (i >= DT * DIN) return;
    int sel = blockIdx.y;
    const float* W = (sel == 0) ? W0 : (sel == 1) ? W1 : (sel == 2) ? W2 : W3;
    int n = i >> 10, k = i & 1023;
    g_Wp[sel][i] = __float2half_rn(__ldg(&W[k * DT + n]));
}
__global__ void prep_wt2(const float* __restrict__ Wa, const float* __restrict__ Wb) {
    __shared__ float t[32][33];
    int oi = blockIdx.x;
    int tri = blockIdx.z;
    const float* W = tri ? Wb : Wa;
    int kt = (blockIdx.y / 5) * 32, jt = (blockIdx.y % 5) * 32;
    int tx = threadIdx.x, ty = threadIdx.y;
    int k = kt + ty, j = jt + tx;
    float v = (k < DT && j < DT) ? W[(size_t)oi * (DT * DT) + k * DT + j] : 0.f;
    t[ty][tx] = v;
    __syncthreads();
    int j2 = jt + ty, k2 = kt + tx;
    if (j2 < DT && k2 < DTP) {
        float u = t[tx][ty];
        size_t d = (size_t)oi * (DT * DTP) + (size_t)j2 * DTP + k2;
        g_Wt[tri][d] = __float2half_rn(u);
    }
}

// ---------------- HMMA GEMM: BM=48, BN=96, BK=32, 192 thr, 4-stage ---------
// One barrier per chunk: [wait, bar, compute, stage(ch+S-1)].
// MODE 0 keeps A hi/lo split (3 smem mats); modes 1-3 single x single (2 mats).
// Warp grid 3(m) x 2(n): each warp 16m x 48n = 6 acc quads.
// MODE 0: proj   x(288x1024) @ Wp[z] -> g_p[z]              (z=sel)
// MODE 1: op1    p0(288xDTP) @ Wt[z] flat N=90000 -> g_w[z]  (z=tri)
// MODE 2: op2    Y @ g_w[tr][b] flat N=86400 -> g_t[tr]      (z=b*2+tr)
// MODE 3: op3    X @ g_t[tr][b] flat N=82944 -> out (+tr ofs) (z=b*2+tr),
//                fused mask+logsoftmax; tr=0 direct, tr=1 transposed coords
template<int MODE, int STAGES>
__global__ __launch_bounds__(192)
void tk(const float* __restrict__ b0s, const float* __restrict__ b1s,
        const float* __restrict__ b2s, const float* __restrict__ b3s,
        float* __restrict__ outp)
{
    constexpr bool ASPLIT = (MODE == 0);
    constexpr int OFFAL = 3840;                         // Al region (split only)
    constexpr int OFFB  = ASPLIT ? 7680 : 3840;
    constexpr int STGc  = OFFB + 7680;                  // 15360 / 11520
    constexpr int NITc  = ASPLIT ? 4 : 3;               // 768 / 576 segments

    extern __shared__ __align__(16) char sm[];

    const int tid  = threadIdx.x;
    const int lane = tid & 31, warp = tid >> 5;
    const int wm = warp >> 1, wn = warp & 1;
    const int bx = blockIdx.x, by = blockIdx.y, zb = blockIdx.z;
    const int m0 = bx * 48, n0 = by * 96;

    const int tr = zb & 1, bb = zb >> 1;
    float* outO = nullptr;
    if constexpr (MODE == 3) outO = outp + (size_t)tr * OUT1N;

    // ---- OP3 fully-masked block: fill constants, skip GEMM ----
    if constexpr (MODE == 3) {
        bool allmask;
        if (!tr) {
            allmask = ((n0 >> 2) / LLn) > (m0 + 47);
        } else {
            allmask = true;
            #pragma unroll 1
            for (int qd = 0; qd < 24; qd++) {
                int nq = (n0 >> 2) + qd;
                if (nq / LLn <= nq % LLn) { allmask = false; break; }
            }
        }
        if (allmask) {
            const float4 c4 = make_float4(LOGQ, LOGQ, LOGQ, LOGQ);
            for (int idx = tid; idx < 48 * 24; idx += 192) {
                int mm = m0 + idx / 24;
                int nq = (n0 >> 2) + idx % 24;
                int z = nq / LLn, t = nq % LLn;
                size_t qb;
                if (!tr) qb = (((size_t)(bb * LLn + z) * LLn + mm) * LLn + t);
                else     qb = (((size_t)(bb * LLn + z) * LLn + t) * LLn + mm);
                ((float4*)outO)[qb] = c4;
            }
            return;
        }
    }

    const __half *Ah, *Al = nullptr, *Bh;
    int pitchA, pitchB, KT, NB;
    if constexpr (MODE == 0) {
        Ah = g_xh; Al = g_xl; Bh = g_Wp[zb];
        pitchA = DIN; pitchB = DIN; KT = 32; NB = DT;
    }
    if constexpr (MODE == 1) {
        Ah = g_p[0]; Bh = g_Wt[zb];
        pitchA = DTP; pitchB = DTP; KT = 5; NB = NFLAT;
    }
    if constexpr (MODE == 2) {
        const int sl = tr ? 1 : 2;                 // tri1: Y=oh, tri2: Y=st
        Ah = g_p[sl] + (size_t)bb * LLn * DTP;
        Bh = g_w[tr] + (size_t)bb * 576 * DT * DTP;
        pitchA = DTP; pitchB = DTP; KT = 5; NB = NF2;
    }
    if constexpr (MODE == 3) {
        Ah = g_p[tr ? 3 : 1] + (size_t)bb * LLn * DTP;
        Bh = g_t[tr] + (size_t)bb * NF3 * DTP;
        pitchA = DTP; pitchB = DTP; KT = 5; NB = NF3;
    }

    const uint32_t sbase = smem_u32(sm);

    // ---- per-thread staging plan: NITc segments of 16B (exact) ----
    const __half* sptr[NITc];
    uint32_t sdst[NITc], ssz[NITc];
    constexpr int NA = ASPLIT ? 384 : 192;
    #pragma unroll
    for (int it = 0; it < NITc; it++) {
        int idx = tid + it * 192;
        if (idx < NA) {
            int mat = idx / 192;                     // 0=Ah 1=Al (split only)
            int rem = idx - mat * 192;
            int row = rem >> 2, seg = rem & 3;
            sptr[it] = ((mat && ASPLIT) ? Al : Ah) + (size_t)(m0 + row) * pitchA + seg * 8;
            sdst[it] = (uint32_t)(mat * OFFAL + row * 80 + seg * 16);
            ssz[it]  = 16;
        } else {
            int brem = idx - NA;                     // 0..383 (B rows 96 x 4 segs)
            int row = brem >> 2, seg = brem & 3;
            int gr = n0 + row;
            bool vv = gr < NB;
            sptr[it] = Bh + (size_t)(vv ? gr : n0) * pitchB + seg * 8;
            sdst[it] = (uint32_t)(OFFB + row * 80 + seg * 16);
            ssz[it]  = vv ? 16u : 0u;
        }
    }

    // ---- ldmatrix lane offsets (pitch-80 rows, conflict-free) ----
    const int q = lane >> 3, r = lane & 7;
    const uint32_t aOff  = (uint32_t)((wm * 16 + ((q & 1) ? 8 : 0) + r) * 80 + ((q >> 1) ? 16 : 0));
    const uint32_t bOff0 = (uint32_t)((wn * 48 + ((lane >> 4) ? 8 : 0) + r) * 80 + ((q & 1) ? 16 : 0));

    // OP3/tri0: warp-level compute skip when warp's m-range fully masked
    bool wskip = false;
    if constexpr (MODE == 3)
        wskip = (!tr) && (((n0 >> 2) / LLn) > (m0 + wm * 16 + 15));

    float acc[6][4];
    #pragma unroll
    for (int i = 0; i < 6; i++)
        #pragma unroll
        for (int j = 0; j < 4; j++) acc[i][j] = 0.f;

    auto stageCh = [&](int buf) {
        const uint32_t sb = sbase + (uint32_t)(buf * STGc);
        #pragma unroll
        for (int it = 0; it < NITc; it++) {
            cpa16(sb + sdst[it], sptr[it], ssz[it]);
            sptr[it] += 32;
        }
        asm volatile("cp.async.commit_group;" ::: "memory");
    };

    // prologue: stage chunks 0..S-2
    #pragma unroll
    for (int s = 0; s < STAGES - 1; s++) stageCh(s);

    for (int ch = 0; ch < KT; ch++) {
        // wait for chunk ch: pending <= min(S-2, KT-1-ch)
        {
            int v = KT - 1 - ch;
            if (STAGES - 2 < v) v = STAGES - 2;
            if (v >= 2) cp_wait<2>();
            else if (v == 1) cp_wait<1>();
            else cp_wait<0>();
        }
        __syncthreads();

        if (!wskip) {
            const uint32_t cb = sbase + (uint32_t)((ch & (STAGES - 1)) * STGc);
            #pragma unroll
            for (int ks = 0; ks < 2; ks++) {
                const uint32_t ko = (uint32_t)(ks * 32);
                // batch all fragment loads first (overlap LDSM latency)
                uint32_t ah[4], al4[4], bh[3][4];
                ldm4(ah, cb + aOff + ko);
                if constexpr (ASPLIT) ldm4(al4, cb + OFFAL + aOff + ko);
                #pragma unroll
                for (int g = 0; g < 3; g++)
                    ldm4(bh[g], cb + OFFB + bOff0 + (uint32_t)(g * 1280) + ko);
                #pragma unroll
                for (int g = 0; g < 3; g++) {
                    mma_f16(acc[2 * g],     ah, bh[g][0], bh[g][1]);
                    mma_f16(acc[2 * g + 1], ah, bh[g][2], bh[g][3]);
                }
                if constexpr (ASPLIT) {
                    #pragma unroll
                    for (int g = 0; g < 3; g++) {
                        mma_f16(acc[2 * g],     al4, bh[g][0], bh[g][1]);
                        mma_f16(acc[2 * g + 1], al4, bh[g][2], bh[g][3]);
                    }
                }
            }
        }

        // stage chunk ch+S-1 into buffer (ch-1)%S -- released by this bar
        if (ch + STAGES - 1 < KT) stageCh((ch + STAGES - 1) & (STAGES - 1));
    }

    // ---- store ----
    const float* bias = nullptr;
    if constexpr (MODE == 0)
        bias = (zb == 0) ? b0s : (zb == 1) ? b1s : (zb == 2) ? b2s : b3s;

    const int g8 = lane >> 2, cc = lane & 3, t2 = cc * 2;
    const int mb = m0 + wm * 16, nbb = n0 + wn * 48;

    if constexpr (MODE <= 2) {
        // pair-packed stores (even n; rows even-width so pairs never straddle)
        #pragma unroll
        for (int j = 0; j < 6; j++) {
            #pragma unroll
            for (int h = 0; h < 2; h++) {
                const int m = mb + g8 + h * 8;
                const int n = nbb + j * 8 + t2;          // even
                const float v0 = acc[j][2 * h], v1 = acc[j][2 * h + 1];
                if constexpr (MODE == 0) {
                    if (n + 1 < DTP) {
                        float a0 = (n < DT) ? v0 + bias[n] : 0.f;
                        float a1 = (n + 1 < DT) ? v1 + bias[n + 1] : 0.f;
                        store_pair1(g_p[zb], (size_t)m * DTP + n, a0, a1);
                    }
                }
                if constexpr (MODE == 1) {
                    if (n < NFLAT) {
                        int oi = n / DT, jj = n - oi * DT;
                        int o = oi / DT, i = oi - o * DT;
                        size_t d = ((size_t)(m * NOUT + o) * DT + i) * DTP + jj;
                        store_pair1(g_w[zb], d, v0, v1);
                    }
                }
                if constexpr (MODE == 2) {
                    int qq = n / DT, i = n - qq * DT;
                    int z = qq >> 2, o = qq & 3;
                    size_t rrow = ((size_t)(z * LLn + m)) * NOUT + o;
                    size_t d = ((size_t)bb * NF3 + rrow) * DTP + i;
                    store_pair1(g_t[tr], d, v0, v1);
                }
            }
        }
    } else {
        // fused mask + log_softmax; one float4 per quad, even-cc lanes store
        #pragma unroll
        for (int j = 0; j < 6; j++) {
            #pragma unroll
            for (int h = 0; h < 2; h++) {
                const float a0 = acc[j][2 * h], a1 = acc[j][2 * h + 1];
                const float p0 = __shfl_xor_sync(0xffffffffu, a0, 1);
                const float p1 = __shfl_xor_sync(0xffffffffu, a1, 1);
                if (!(cc & 1)) {
                    const int nq = (nbb + j * 8 + ((cc == 2) ? 4 : 0)) >> 2;
                    const int z = nq / LLn, t = nq - z * LLn;
                    const int m = mb + g8 + h * 8;
                    const bool keep = tr ? (z <= t) : (z <= m);
                    float4 r4;
                    if (keep) r4 = lsm4(a0, a1, p0, p1);
                    else      r4 = make_float4(LOGQ, LOGQ, LOGQ, LOGQ);
                    size_t qb;
                    if (!tr) qb = (((size_t)(bb * LLn + z) * LLn + m) * LLn + t);
                    else     qb = (((size_t)(bb * LLn + z) * LLn + t) * LLn + m);
                    ((float4*)outO)[qb] = r4;
                }
            }
        }
    }
}

// ---------------------------------------------------------------------------
extern "C" void kernel_launch(void* const* d_in, const int* in_sizes, int n_in,
                              void* d_out, int out_size)
{
    const float* x     = (const float*)d_in[0];
    const float* W_sh  = (const float*)d_in[1];
    const float* b_sh  = (const float*)d_in[2];
    const float* W_st  = (const float*)d_in[3];
    const float* b_st  = (const float*)d_in[4];
    const float* W_oh  = (const float*)d_in[5];
    const float* b_oh  = (const float*)d_in[6];
    const float* W_ot  = (const float*)d_in[7];
    const float* b_ot  = (const float*)d_in[8];
    const float* W_t1  = (const float*)d_in[9];
    const float* W_t2  = (const float*)d_in[10];
    float* out = (float*)d_out;

    cudaFuncSetAttribute(tk<0, 4>, cudaFuncAttributeMaxDynamicSharedMemorySize, 4 * 15360);
    cudaFuncSetAttribute(tk<1, 4>, cudaFuncAttributeMaxDynamicSharedMemorySize, 4 * 11520);
    cudaFuncSetAttribute(tk<2, 4>, cudaFuncAttributeMaxDynamicSharedMemorySize, 4 * 11520);
    cudaFuncSetAttribute(tk<3, 4>, cudaFuncAttributeMaxDynamicSharedMemorySize, 4 * 11520);

    // prep: fp16 conversions (x h/l split; weights single)
    prep_x<<<(BL * DIN + 255) / 256, 256>>>(x);
    prep_pw4<<<dim3((DT * DIN + 255) / 256, 4), 256>>>(W_sh, W_st, W_oh, W_ot);
    prep_wt2<<<dim3(OI, 25, 2), dim3(32, 32)>>>(W_t1, W_t2);

    // projections: M=288 (6x48) x N=150 (2x96) x 4 sel
    tk<0, 4><<<dim3(6, 2, 4), 192, 4 * 15360>>>(b_sh, b_st, b_oh, b_ot, nullptr);

    // op1 both tris:  z = tri
    tk<1, 4><<<dim3(6, 938, 2), 192, 4 * 11520>>>(nullptr, nullptr, nullptr, nullptr, nullptr);
    // op2 both tris x both batches: z = b*2 + tri
    tk<2, 4><<<dim3(3, 900, 4), 192, 4 * 11520>>>(nullptr, nullptr, nullptr, nullptr, nullptr);
    // op3 both tris x both batches (merged): z = b*2 + tri
    tk<3, 4><<<dim3(3, 864, 4), 192, 4 * 11520>>>(nullptr, nullptr, nullptr, nullptr, out);
}